// round 6
// baseline (speedup 1.0000x reference)
#include <cuda_runtime.h>
#include <cuda_fp16.h>
#include <cstdint>

// Model_62886911148434 — seed-guided cluster loss.
// A: gather + mean-pool both tables in one pass; explicit 8-wide load batches
//    (forces high per-thread MLP in SASS instead of trusting unroll)
// B: mma.sync m16n8k16 fp16 GEMM (128x128 tiles, grid.z=2) + per-cluster max
// C: warp-per-sentence softmax/loss + fused deterministic reduction

#define B_ 2048
#define S_ 2048
#define L_ 64
#define LS_ 8
#define D_ 300
#define DP2 320          // padded K (zeros in 300..319): 5 chunks of 64 halfs
#define C_ 64
#define NCHUNK 5
#define LOSS_BLOCKS 256

__device__ __half g_snt[2][B_ * DP2];
__device__ __half g_sd [2][S_ * DP2];
__device__ float g_pmax[2][B_ * C_];
__device__ float g_lossb[B_];
__device__ unsigned int g_cnt;   // zero-initialized; reset by last block

__device__ __forceinline__ uint32_t smem_u32(const void* p) {
    uint32_t a;
    asm("{ .reg .u64 t; cvta.to.shared.u64 t, %1; cvt.u32.u64 %0, t; }"
        : "=r"(a) : "l"(p));
    return a;
}

// ---------------- Stage A: embeddings (fp32 accumulate -> fp16 store) --------
// One block per row, 96 threads (75 active float4 lanes). Tokens staged in
// smem. Batches of 4 tokens x 2 tables = 8 independent LDG.128 held in named
// register arrays before any FMA touches them.
__global__ void __launch_bounds__(96) emb_kernel(
    const int* __restrict__ sents, const int* __restrict__ seeds,
    const float* __restrict__ mask,
    const float* __restrict__ embT, const float* __restrict__ embS)
{
    __shared__ int   s_tok[L_];
    __shared__ float s_msk[L_];

    const int row = blockIdx.x;
    const int f = threadIdx.x;
    const bool act = (f < 75);
    float4 at = make_float4(0.f, 0.f, 0.f, 0.f);
    float4 as = make_float4(0.f, 0.f, 0.f, 0.f);

    float sc;
    __half* d0;
    __half* d1;

    if (row < B_) {
        if (f < L_) {
            s_tok[f] = sents[row * L_ + f];
            s_msk[f] = mask [row * L_ + f];
        }
        __syncthreads();

        if (act) {
            #pragma unroll
            for (int l0 = 0; l0 < L_; l0 += 4) {
                float4 vt[4], vs[4];
                #pragma unroll
                for (int j = 0; j < 4; j++) {
                    const int tok = s_tok[l0 + j];
                    vt[j] = *(const float4*)(embT + (size_t)tok * D_ + f * 4);
                    vs[j] = *(const float4*)(embS + (size_t)tok * D_ + f * 4);
                }
                #pragma unroll
                for (int j = 0; j < 4; j++) {
                    const float m = s_msk[l0 + j];
                    at.x += vt[j].x * m; at.y += vt[j].y * m;
                    at.z += vt[j].z * m; at.w += vt[j].w * m;
                    as.x += vs[j].x * m; as.y += vs[j].y * m;
                    as.z += vs[j].z * m; as.w += vs[j].w * m;
                }
            }
        }
        float msum = 0.f;
        #pragma unroll
        for (int l = 0; l < L_; l++) msum += s_msk[l];
        sc = 1.f / fmaxf(msum, 1.f);
        d0 = &g_snt[0][row * DP2];
        d1 = &g_snt[1][row * DP2];
    } else {
        const int s = row - B_;
        if (f < LS_) s_tok[f] = seeds[s * LS_ + f];
        __syncthreads();

        if (act) {
            float4 vt[8], vs[8];
            #pragma unroll
            for (int j = 0; j < 8; j++) {
                const int tok = s_tok[j];
                vt[j] = *(const float4*)(embT + (size_t)tok * D_ + f * 4);
                vs[j] = *(const float4*)(embS + (size_t)tok * D_ + f * 4);
            }
            #pragma unroll
            for (int j = 0; j < 8; j++) {
                at.x += vt[j].x; at.y += vt[j].y; at.z += vt[j].z; at.w += vt[j].w;
                as.x += vs[j].x; as.y += vs[j].y; as.z += vs[j].z; as.w += vs[j].w;
            }
        }
        sc = 1.f / (float)LS_;
        d0 = &g_sd[0][s * DP2];
        d1 = &g_sd[1][s * DP2];
    }

    if (act) {
        ((__half2*)(d0 + f * 4))[0] = __floats2half2_rn(at.x * sc, at.y * sc);
        ((__half2*)(d0 + f * 4))[1] = __floats2half2_rn(at.z * sc, at.w * sc);
        ((__half2*)(d1 + f * 4))[0] = __floats2half2_rn(as.x * sc, as.y * sc);
        ((__half2*)(d1 + f * 4))[1] = __floats2half2_rn(as.z * sc, as.w * sc);
    } else if (f < 80) {
        const __half2 z = __floats2half2_rn(0.f, 0.f);
        ((__half2*)(d0 + f * 4))[0] = z;
        ((__half2*)(d0 + f * 4))[1] = z;
        ((__half2*)(d1 + f * 4))[0] = z;
        ((__half2*)(d1 + f * 4))[1] = z;
    }
}

// ---------------- Stage B: mma.sync fp16 GEMM + per-cluster max ----------------
// Block: 256 threads (8 warps, 2x4), tile 128(m) x 128(n), warp tile 64x32.
// n-range of a warp = exactly one 32-seed cluster -> max is warp-local.
__global__ void __launch_bounds__(256, 2) gemm_max_kernel()
{
    __shared__ __align__(128) uint4 smA[1024];   // 128 rows x 64 halfs (swizzled)
    __shared__ __align__(128) uint4 smB[1024];

    const int tid = threadIdx.x;
    const int wid = tid >> 5, lane = tid & 31;
    const int warp_m = wid >> 2, warp_n = wid & 3;
    const int z = blockIdx.z, bcol = blockIdx.x, brow = blockIdx.y;

    const __half* Ag = &g_snt[z][(size_t)brow * 128 * DP2];
    const __half* Bg = &g_sd [z][(size_t)bcol * 128 * DP2];

    int srow[4], sidx[4];
    #pragma unroll
    for (int it = 0; it < 4; it++) {
        const int i = it * 256 + tid;
        srow[it] = i >> 3;
        sidx[it] = (i >> 3) * 8 + ((i & 7) ^ ((i >> 3) & 7));
    }

    const uint32_t aBase = smem_u32(smA);
    const uint32_t bBase = smem_u32(smB);
    uint32_t preA[4]; int a7[4];
    #pragma unroll
    for (int mf = 0; mf < 4; mf++) {
        const int rA = warp_m * 64 + mf * 16 + (lane & 7) + ((lane >> 3) & 1) * 8;
        preA[mf] = aBase + rA * 128;
        a7[mf] = rA & 7;
    }
    const int cA = lane >> 4;
    uint32_t preB[2]; int b7[2];
    #pragma unroll
    for (int g = 0; g < 2; g++) {
        const int rB = warp_n * 32 + g * 16 + (lane & 7) + (lane >> 4) * 8;
        preB[g] = bBase + rB * 128;
        b7[g] = rB & 7;
    }
    const int cB = (lane >> 3) & 1;

    float acc[4][4][4];
    #pragma unroll
    for (int mf = 0; mf < 4; mf++)
        #pragma unroll
        for (int nf = 0; nf < 4; nf++)
            #pragma unroll
            for (int r = 0; r < 4; r++) acc[mf][nf][r] = 0.f;

    uint4 ra[4], rb[4];
    #pragma unroll
    for (int it = 0; it < 4; it++) {
        const int i = it * 256 + tid;
        ra[it] = *(const uint4*)(Ag + (size_t)srow[it] * DP2 + (i & 7) * 8);
        rb[it] = *(const uint4*)(Bg + (size_t)srow[it] * DP2 + (i & 7) * 8);
    }

    for (int ch = 0; ch < NCHUNK; ch++) {
        __syncthreads();
        #pragma unroll
        for (int it = 0; it < 4; it++) {
            smA[sidx[it]] = ra[it];
            smB[sidx[it]] = rb[it];
        }
        __syncthreads();

        if (ch + 1 < NCHUNK) {
            const int kc = (ch + 1) * 64;
            #pragma unroll
            for (int it = 0; it < 4; it++) {
                const int i = it * 256 + tid;
                ra[it] = *(const uint4*)(Ag + (size_t)srow[it] * DP2 + kc + (i & 7) * 8);
                rb[it] = *(const uint4*)(Bg + (size_t)srow[it] * DP2 + kc + (i & 7) * 8);
            }
        }

        #pragma unroll
        for (int s = 0; s < 4; s++) {
            uint32_t af[4][4];
            #pragma unroll
            for (int mf = 0; mf < 4; mf++) {
                const uint32_t addr = preA[mf] + ((uint32_t)(((2 * s + cA) ^ a7[mf]) << 4));
                asm volatile("ldmatrix.sync.aligned.m8n8.x4.shared.b16 {%0,%1,%2,%3}, [%4];"
                    : "=r"(af[mf][0]), "=r"(af[mf][1]), "=r"(af[mf][2]), "=r"(af[mf][3])
                    : "r"(addr));
            }
            uint32_t bf[2][4];
            #pragma unroll
            for (int g = 0; g < 2; g++) {
                const uint32_t addr = preB[g] + ((uint32_t)(((2 * s + cB) ^ b7[g]) << 4));
                asm volatile("ldmatrix.sync.aligned.m8n8.x4.shared.b16 {%0,%1,%2,%3}, [%4];"
                    : "=r"(bf[g][0]), "=r"(bf[g][1]), "=r"(bf[g][2]), "=r"(bf[g][3])
                    : "r"(addr));
            }
            #pragma unroll
            for (int mf = 0; mf < 4; mf++)
                #pragma unroll
                for (int nf = 0; nf < 4; nf++) {
                    const uint32_t b0 = bf[nf >> 1][(nf & 1) * 2 + 0];
                    const uint32_t b1 = bf[nf >> 1][(nf & 1) * 2 + 1];
                    asm volatile(
                        "mma.sync.aligned.m16n8k16.row.col.f32.f16.f16.f32 "
                        "{%0,%1,%2,%3}, {%4,%5,%6,%7}, {%8,%9}, {%0,%1,%2,%3};"
                        : "+f"(acc[mf][nf][0]), "+f"(acc[mf][nf][1]),
                          "+f"(acc[mf][nf][2]), "+f"(acc[mf][nf][3])
                        : "r"(af[mf][0]), "r"(af[mf][1]), "r"(af[mf][2]), "r"(af[mf][3]),
                          "r"(b0), "r"(b1));
                }
        }
    }

    const int cluster = bcol * 4 + warp_n;
    #pragma unroll
    for (int mf = 0; mf < 4; mf++) {
        float mlo = -3.402823466e38f, mhi = -3.402823466e38f;
        #pragma unroll
        for (int nf = 0; nf < 4; nf++) {
            mlo = fmaxf(mlo, fmaxf(acc[mf][nf][0], acc[mf][nf][1]));
            mhi = fmaxf(mhi, fmaxf(acc[mf][nf][2], acc[mf][nf][3]));
        }
        mlo = fmaxf(mlo, __shfl_xor_sync(0xffffffffu, mlo, 1));
        mlo = fmaxf(mlo, __shfl_xor_sync(0xffffffffu, mlo, 2));
        mhi = fmaxf(mhi, __shfl_xor_sync(0xffffffffu, mhi, 1));
        mhi = fmaxf(mhi, __shfl_xor_sync(0xffffffffu, mhi, 2));
        if ((lane & 3) == 0) {
            const int grow = brow * 128 + warp_m * 64 + mf * 16 + (lane >> 2);
            g_pmax[z][grow * C_ + cluster] = mlo;
            g_pmax[z][(grow + 8) * C_ + cluster] = mhi;
        }
    }
}

// ---------------- Stage C: warp-per-sentence loss + fused reduction ----------
// 256 blocks x 256 threads; warp w handles sentence blockIdx.x*8 + w.
// Each lane owns clusters {lane, lane+32}. Shfl-only reductions.
__global__ void __launch_bounds__(256) loss_kernel(float* __restrict__ out)
{
    const int tid = threadIdx.x;
    const int lane = tid & 31, w = tid >> 5;
    const int b = blockIdx.x * 8 + w;

    const float t0 = g_pmax[0][b * C_ + lane];
    const float t1 = g_pmax[0][b * C_ + 32 + lane];
    const float s0 = g_pmax[1][b * C_ + lane];
    const float s1 = g_pmax[1][b * C_ + 32 + lane];

    float m = fmaxf(t0, t1);
    #pragma unroll
    for (int o = 16; o > 0; o >>= 1)
        m = fmaxf(m, __shfl_xor_sync(0xffffffffu, m, o));

    const float e0 = expf(t0 - m);
    const float e1 = expf(t1 - m);
    float Z = e0 + e1;
    #pragma unroll
    for (int o = 16; o > 0; o >>= 1)
        Z += __shfl_xor_sync(0xffffffffu, Z, o);

    const float inv_Z = 1.f / Z;
    const float reli = inv_Z - (1.f / (float)C_);   // max prob = exp(0)/Z
    const float wgt = 1.f + 0.5f * fabsf(reli);
    const float d0 = e0 * inv_Z - s0;
    const float d1 = e1 * inv_Z - s1;
    float q = d0 * d0 + d1 * d1;
    #pragma unroll
    for (int o = 16; o > 0; o >>= 1)
        q += __shfl_xor_sync(0xffffffffu, q, o);
    if (lane == 0) g_lossb[b] = wgt * q;

    // last-block-done fused reduction (deterministic fixed-order sum)
    __shared__ int is_last;
    __shared__ float sh[8];
    __threadfence();
    __syncthreads();
    if (tid == 0) {
        const unsigned int o = atomicAdd(&g_cnt, 1u);
        is_last = (o == (unsigned int)(LOSS_BLOCKS - 1));
    }
    __syncthreads();
    if (is_last) {
        __threadfence();
        float sum = 0.f;
        for (int i = tid; i < B_; i += 256) sum += g_lossb[i];
        #pragma unroll
        for (int o = 16; o > 0; o >>= 1)
            sum += __shfl_xor_sync(0xffffffffu, sum, o);
        if (lane == 0) sh[w] = sum;
        __syncthreads();
        if (tid == 0) {
            float tot = 0.f;
            #pragma unroll
            for (int i = 0; i < 8; i++) tot += sh[i];
            out[0] = tot * (1.f / (float)B_);
            g_cnt = 0;   // reset for next graph replay
        }
    }
}

extern "C" void kernel_launch(void* const* d_in, const int* in_sizes, int n_in,
                              void* d_out, int out_size)
{
    const int* sents = nullptr;
    const int* seeds = nullptr;
    const float* mask = nullptr;
    const float* embT = nullptr;
    const float* embS = nullptr;
    int c131 = 0, c15m = 0;
    for (int i = 0; i < n_in; i++) {
        const int sz = in_sizes[i];
        if (sz == B_ * L_) {
            if (c131 == 0) sents = (const int*)d_in[i];
            else           mask  = (const float*)d_in[i];
            c131++;
        } else if (sz == S_ * LS_) {
            seeds = (const int*)d_in[i];
        } else if (sz == 50000 * D_) {
            if (c15m == 0) embT = (const float*)d_in[i];
            else           embS = (const float*)d_in[i];
            c15m++;
        }
    }

    emb_kernel<<<B_ + S_, 96>>>(sents, seeds, mask, embT, embS);
    gemm_max_kernel<<<dim3(16, 16, 2), 256>>>();
    loss_kernel<<<LOSS_BLOCKS, 256>>>((float*)d_out);
}

// round 7
// speedup vs baseline: 1.0264x; 1.0264x over previous
#include <cuda_runtime.h>
#include <cuda_fp16.h>
#include <cstdint>

// Model_62886911148434 — seed-guided cluster loss.
// A: gather + mean-pool; 2-token load batches (MLP~4 at ~48 regs, occ kept high)
// B: mma.sync m16n8k16 fp16 GEMM, 128x128 tiles, double-buffered smem (1 sync/chunk)
// C: warp-per-sentence softmax/loss + fused deterministic reduction

#define B_ 2048
#define S_ 2048
#define L_ 64
#define LS_ 8
#define D_ 300
#define DP2 320          // padded K (zeros in 300..319): 5 chunks of 64 halfs
#define C_ 64
#define NCHUNK 5
#define LOSS_BLOCKS 256
#define GEMM_SMEM (64 * 1024)   // 2 stages x (A 16KB + B 16KB)

__device__ __half g_snt[2][B_ * DP2];
__device__ __half g_sd [2][S_ * DP2];
__device__ float g_pmax[2][B_ * C_];
__device__ float g_lossb[B_];
__device__ unsigned int g_cnt;   // zero-initialized; reset by last block

__device__ __forceinline__ uint32_t smem_u32(const void* p) {
    uint32_t a;
    asm("{ .reg .u64 t; cvta.to.shared.u64 t, %1; cvt.u32.u64 %0, t; }"
        : "=r"(a) : "l"(p));
    return a;
}

// ---------------- Stage A: embeddings (fp32 accumulate -> fp16 store) --------
// One block per row, 96 threads (75 active float4 lanes). Tokens staged in
// smem. 2-token x 2-table batches: 4 independent LDG.128 in flight with only
// ~16 data registers, keeping occupancy high.
__global__ void __launch_bounds__(96) emb_kernel(
    const int* __restrict__ sents, const int* __restrict__ seeds,
    const float* __restrict__ mask,
    const float* __restrict__ embT, const float* __restrict__ embS)
{
    __shared__ int   s_tok[L_];
    __shared__ float s_msk[L_];

    const int row = blockIdx.x;
    const int f = threadIdx.x;
    const bool act = (f < 75);
    float4 at = make_float4(0.f, 0.f, 0.f, 0.f);
    float4 as = make_float4(0.f, 0.f, 0.f, 0.f);

    float sc;
    __half* d0;
    __half* d1;

    if (row < B_) {
        if (f < L_) {
            s_tok[f] = sents[row * L_ + f];
            s_msk[f] = mask [row * L_ + f];
        }
        __syncthreads();

        if (act) {
            #pragma unroll
            for (int l0 = 0; l0 < L_; l0 += 2) {
                const int t0 = s_tok[l0], t1 = s_tok[l0 + 1];
                const float4 vt0 = *(const float4*)(embT + (size_t)t0 * D_ + f * 4);
                const float4 vs0 = *(const float4*)(embS + (size_t)t0 * D_ + f * 4);
                const float4 vt1 = *(const float4*)(embT + (size_t)t1 * D_ + f * 4);
                const float4 vs1 = *(const float4*)(embS + (size_t)t1 * D_ + f * 4);
                const float m0 = s_msk[l0], m1 = s_msk[l0 + 1];
                at.x += vt0.x * m0; at.y += vt0.y * m0;
                at.z += vt0.z * m0; at.w += vt0.w * m0;
                as.x += vs0.x * m0; as.y += vs0.y * m0;
                as.z += vs0.z * m0; as.w += vs0.w * m0;
                at.x += vt1.x * m1; at.y += vt1.y * m1;
                at.z += vt1.z * m1; at.w += vt1.w * m1;
                as.x += vs1.x * m1; as.y += vs1.y * m1;
                as.z += vs1.z * m1; as.w += vs1.w * m1;
            }
        }
        float msum = 0.f;
        #pragma unroll
        for (int l = 0; l < L_; l++) msum += s_msk[l];
        sc = 1.f / fmaxf(msum, 1.f);
        d0 = &g_snt[0][row * DP2];
        d1 = &g_snt[1][row * DP2];
    } else {
        const int s = row - B_;
        if (f < LS_) s_tok[f] = seeds[s * LS_ + f];
        __syncthreads();

        if (act) {
            #pragma unroll
            for (int l0 = 0; l0 < LS_; l0 += 2) {
                const int t0 = s_tok[l0], t1 = s_tok[l0 + 1];
                const float4 vt0 = *(const float4*)(embT + (size_t)t0 * D_ + f * 4);
                const float4 vs0 = *(const float4*)(embS + (size_t)t0 * D_ + f * 4);
                const float4 vt1 = *(const float4*)(embT + (size_t)t1 * D_ + f * 4);
                const float4 vs1 = *(const float4*)(embS + (size_t)t1 * D_ + f * 4);
                at.x += vt0.x + vt1.x; at.y += vt0.y + vt1.y;
                at.z += vt0.z + vt1.z; at.w += vt0.w + vt1.w;
                as.x += vs0.x + vs1.x; as.y += vs0.y + vs1.y;
                as.z += vs0.z + vs1.z; as.w += vs0.w + vs1.w;
            }
        }
        sc = 1.f / (float)LS_;
        d0 = &g_sd[0][s * DP2];
        d1 = &g_sd[1][s * DP2];
    }

    if (act) {
        ((__half2*)(d0 + f * 4))[0] = __floats2half2_rn(at.x * sc, at.y * sc);
        ((__half2*)(d0 + f * 4))[1] = __floats2half2_rn(at.z * sc, at.w * sc);
        ((__half2*)(d1 + f * 4))[0] = __floats2half2_rn(as.x * sc, as.y * sc);
        ((__half2*)(d1 + f * 4))[1] = __floats2half2_rn(as.z * sc, as.w * sc);
    } else if (f < 80) {
        const __half2 z = __floats2half2_rn(0.f, 0.f);
        ((__half2*)(d0 + f * 4))[0] = z;
        ((__half2*)(d0 + f * 4))[1] = z;
        ((__half2*)(d1 + f * 4))[0] = z;
        ((__half2*)(d1 + f * 4))[1] = z;
    }
}

// ---------------- Stage B: mma.sync fp16 GEMM + per-cluster max ----------------
// Block: 256 threads (8 warps, 2x4), tile 128(m) x 128(n), warp tile 64x32.
// Double-buffered smem stages -> one __syncthreads per K-chunk; STS of chunk
// ch+1 overlaps the MMAs of chunk ch.
__global__ void __launch_bounds__(256, 2) gemm_max_kernel()
{
    extern __shared__ __align__(16) uint4 smem_dyn[];  // [2][2048]: stage s: A@s*2048, B@s*2048+1024

    const int tid = threadIdx.x;
    const int wid = tid >> 5, lane = tid & 31;
    const int warp_m = wid >> 2, warp_n = wid & 3;
    const int z = blockIdx.z, bcol = blockIdx.x, brow = blockIdx.y;

    const __half* Ag = &g_snt[z][(size_t)brow * 128 * DP2];
    const __half* Bg = &g_sd [z][(size_t)bcol * 128 * DP2];

    int srow[4], sidx[4];
    #pragma unroll
    for (int it = 0; it < 4; it++) {
        const int i = it * 256 + tid;
        srow[it] = i >> 3;
        sidx[it] = (i >> 3) * 8 + ((i & 7) ^ ((i >> 3) & 7));
    }

    const uint32_t aBase = smem_u32(smem_dyn);
    const uint32_t bBase = aBase + 16384u;
    uint32_t preA[4]; int a7[4];
    #pragma unroll
    for (int mf = 0; mf < 4; mf++) {
        const int rA = warp_m * 64 + mf * 16 + (lane & 7) + ((lane >> 3) & 1) * 8;
        preA[mf] = aBase + rA * 128;
        a7[mf] = rA & 7;
    }
    const int cA = lane >> 4;
    uint32_t preB[2]; int b7[2];
    #pragma unroll
    for (int g = 0; g < 2; g++) {
        const int rB = warp_n * 32 + g * 16 + (lane & 7) + (lane >> 4) * 8;
        preB[g] = bBase + rB * 128;
        b7[g] = rB & 7;
    }
    const int cB = (lane >> 3) & 1;

    float acc[4][4][4];
    #pragma unroll
    for (int mf = 0; mf < 4; mf++)
        #pragma unroll
        for (int nf = 0; nf < 4; nf++)
            #pragma unroll
            for (int r = 0; r < 4; r++) acc[mf][nf][r] = 0.f;

    // prologue: load + store chunk 0 into stage 0
    uint4 ra[4], rb[4];
    #pragma unroll
    for (int it = 0; it < 4; it++) {
        const int i = it * 256 + tid;
        ra[it] = *(const uint4*)(Ag + (size_t)srow[it] * DP2 + (i & 7) * 8);
        rb[it] = *(const uint4*)(Bg + (size_t)srow[it] * DP2 + (i & 7) * 8);
    }
    #pragma unroll
    for (int it = 0; it < 4; it++) {
        smem_dyn[sidx[it]] = ra[it];
        smem_dyn[1024 + sidx[it]] = rb[it];
    }

    for (int ch = 0; ch < NCHUNK; ch++) {
        if (ch + 1 < NCHUNK) {
            const int kc = (ch + 1) * 64;
            #pragma unroll
            for (int it = 0; it < 4; it++) {
                const int i = it * 256 + tid;
                ra[it] = *(const uint4*)(Ag + (size_t)srow[it] * DP2 + kc + (i & 7) * 8);
                rb[it] = *(const uint4*)(Bg + (size_t)srow[it] * DP2 + kc + (i & 7) * 8);
            }
        }
        __syncthreads();   // stage[ch&1] now visible to all warps

        const uint32_t stOff = (uint32_t)(ch & 1) * 32768u;
        #pragma unroll
        for (int s = 0; s < 4; s++) {
            uint32_t af[4][4];
            #pragma unroll
            for (int mf = 0; mf < 4; mf++) {
                const uint32_t addr = preA[mf] + stOff + ((uint32_t)(((2 * s + cA) ^ a7[mf]) << 4));
                asm volatile("ldmatrix.sync.aligned.m8n8.x4.shared.b16 {%0,%1,%2,%3}, [%4];"
                    : "=r"(af[mf][0]), "=r"(af[mf][1]), "=r"(af[mf][2]), "=r"(af[mf][3])
                    : "r"(addr));
            }
            uint32_t bf[2][4];
            #pragma unroll
            for (int g = 0; g < 2; g++) {
                const uint32_t addr = preB[g] + stOff + ((uint32_t)(((2 * s + cB) ^ b7[g]) << 4));
                asm volatile("ldmatrix.sync.aligned.m8n8.x4.shared.b16 {%0,%1,%2,%3}, [%4];"
                    : "=r"(bf[g][0]), "=r"(bf[g][1]), "=r"(bf[g][2]), "=r"(bf[g][3])
                    : "r"(addr));
            }
            #pragma unroll
            for (int mf = 0; mf < 4; mf++)
                #pragma unroll
                for (int nf = 0; nf < 4; nf++) {
                    const uint32_t b0 = bf[nf >> 1][(nf & 1) * 2 + 0];
                    const uint32_t b1 = bf[nf >> 1][(nf & 1) * 2 + 1];
                    asm volatile(
                        "mma.sync.aligned.m16n8k16.row.col.f32.f16.f16.f32 "
                        "{%0,%1,%2,%3}, {%4,%5,%6,%7}, {%8,%9}, {%0,%1,%2,%3};"
                        : "+f"(acc[mf][nf][0]), "+f"(acc[mf][nf][1]),
                          "+f"(acc[mf][nf][2]), "+f"(acc[mf][nf][3])
                        : "r"(af[mf][0]), "r"(af[mf][1]), "r"(af[mf][2]), "r"(af[mf][3]),
                          "r"(b0), "r"(b1));
                }
        }

        if (ch + 1 < NCHUNK) {
            const uint32_t nx = (uint32_t)((ch + 1) & 1) * 2048u;
            #pragma unroll
            for (int it = 0; it < 4; it++) {
                smem_dyn[nx + sidx[it]] = ra[it];
                smem_dyn[nx + 1024 + sidx[it]] = rb[it];
            }
        }
    }

    const int cluster = bcol * 4 + warp_n;
    #pragma unroll
    for (int mf = 0; mf < 4; mf++) {
        float mlo = -3.402823466e38f, mhi = -3.402823466e38f;
        #pragma unroll
        for (int nf = 0; nf < 4; nf++) {
            mlo = fmaxf(mlo, fmaxf(acc[mf][nf][0], acc[mf][nf][1]));
            mhi = fmaxf(mhi, fmaxf(acc[mf][nf][2], acc[mf][nf][3]));
        }
        mlo = fmaxf(mlo, __shfl_xor_sync(0xffffffffu, mlo, 1));
        mlo = fmaxf(mlo, __shfl_xor_sync(0xffffffffu, mlo, 2));
        mhi = fmaxf(mhi, __shfl_xor_sync(0xffffffffu, mhi, 1));
        mhi = fmaxf(mhi, __shfl_xor_sync(0xffffffffu, mhi, 2));
        if ((lane & 3) == 0) {
            const int grow = brow * 128 + warp_m * 64 + mf * 16 + (lane >> 2);
            g_pmax[z][grow * C_ + cluster] = mlo;
            g_pmax[z][(grow + 8) * C_ + cluster] = mhi;
        }
    }
}

// ---------------- Stage C: warp-per-sentence loss + fused reduction ----------
__global__ void __launch_bounds__(256) loss_kernel(float* __restrict__ out)
{
    const int tid = threadIdx.x;
    const int lane = tid & 31, w = tid >> 5;
    const int b = blockIdx.x * 8 + w;

    const float t0 = g_pmax[0][b * C_ + lane];
    const float t1 = g_pmax[0][b * C_ + 32 + lane];
    const float s0 = g_pmax[1][b * C_ + lane];
    const float s1 = g_pmax[1][b * C_ + 32 + lane];

    float m = fmaxf(t0, t1);
    #pragma unroll
    for (int o = 16; o > 0; o >>= 1)
        m = fmaxf(m, __shfl_xor_sync(0xffffffffu, m, o));

    const float e0 = expf(t0 - m);
    const float e1 = expf(t1 - m);
    float Z = e0 + e1;
    #pragma unroll
    for (int o = 16; o > 0; o >>= 1)
        Z += __shfl_xor_sync(0xffffffffu, Z, o);

    const float inv_Z = 1.f / Z;
    const float reli = inv_Z - (1.f / (float)C_);   // max prob = exp(0)/Z
    const float wgt = 1.f + 0.5f * fabsf(reli);
    const float d0 = e0 * inv_Z - s0;
    const float d1 = e1 * inv_Z - s1;
    float q = d0 * d0 + d1 * d1;
    #pragma unroll
    for (int o = 16; o > 0; o >>= 1)
        q += __shfl_xor_sync(0xffffffffu, q, o);
    if (lane == 0) g_lossb[b] = wgt * q;

    __shared__ int is_last;
    __shared__ float sh[8];
    __threadfence();
    __syncthreads();
    if (tid == 0) {
        const unsigned int o = atomicAdd(&g_cnt, 1u);
        is_last = (o == (unsigned int)(LOSS_BLOCKS - 1));
    }
    __syncthreads();
    if (is_last) {
        __threadfence();
        float sum = 0.f;
        for (int i = tid; i < B_; i += 256) sum += g_lossb[i];
        #pragma unroll
        for (int o = 16; o > 0; o >>= 1)
            sum += __shfl_xor_sync(0xffffffffu, sum, o);
        if (lane == 0) sh[w] = sum;
        __syncthreads();
        if (tid == 0) {
            float tot = 0.f;
            #pragma unroll
            for (int i = 0; i < 8; i++) tot += sh[i];
            out[0] = tot * (1.f / (float)B_);
            g_cnt = 0;   // reset for next graph replay
        }
    }
}

extern "C" void kernel_launch(void* const* d_in, const int* in_sizes, int n_in,
                              void* d_out, int out_size)
{
    const int* sents = nullptr;
    const int* seeds = nullptr;
    const float* mask = nullptr;
    const float* embT = nullptr;
    const float* embS = nullptr;
    int c131 = 0, c15m = 0;
    for (int i = 0; i < n_in; i++) {
        const int sz = in_sizes[i];
        if (sz == B_ * L_) {
            if (c131 == 0) sents = (const int*)d_in[i];
            else           mask  = (const float*)d_in[i];
            c131++;
        } else if (sz == S_ * LS_) {
            seeds = (const int*)d_in[i];
        } else if (sz == 50000 * D_) {
            if (c15m == 0) embT = (const float*)d_in[i];
            else           embS = (const float*)d_in[i];
            c15m++;
        }
    }

    cudaFuncSetAttribute(gemm_max_kernel,
                         cudaFuncAttributeMaxDynamicSharedMemorySize, GEMM_SMEM);

    emb_kernel<<<B_ + S_, 96>>>(sents, seeds, mask, embT, embS);
    gemm_max_kernel<<<dim3(16, 16, 2), 256, GEMM_SMEM>>>();
    loss_kernel<<<LOSS_BLOCKS, 256>>>((float*)d_out);
}

// round 8
// speedup vs baseline: 1.1187x; 1.0899x over previous
#include <cuda_runtime.h>
#include <cuda_fp16.h>
#include <cstdint>

// Model_62886911148434 — seed-guided cluster loss.
// A: gather + mean-pool (round-4 form: plain loop + unroll 8 -> regs=32, occ~73%)
// B: mma.sync m16n8k16 fp16 GEMM, 128x128 tiles, double-buffered smem (1 sync/chunk)
// C: warp-per-sentence softmax/loss + fused deterministic reduction

#define B_ 2048
#define S_ 2048
#define L_ 64
#define LS_ 8
#define D_ 300
#define DP2 320          // padded K (zeros in 300..319): 5 chunks of 64 halfs
#define C_ 64
#define NCHUNK 5
#define LOSS_BLOCKS 256
#define GEMM_SMEM (64 * 1024)   // 2 stages x (A 16KB + B 16KB)

__device__ __half g_snt[2][B_ * DP2];
__device__ __half g_sd [2][S_ * DP2];
__device__ float g_pmax[2][B_ * C_];
__device__ float g_lossb[B_];
__device__ unsigned int g_cnt;   // zero-initialized; reset by last block

__device__ __forceinline__ uint32_t smem_u32(const void* p) {
    uint32_t a;
    asm("{ .reg .u64 t; cvta.to.shared.u64 t, %1; cvt.u32.u64 %0, t; }"
        : "=r"(a) : "l"(p));
    return a;
}

// ---------------- Stage A: embeddings (fp32 accumulate -> fp16 store) --------
// One block per row. Tokens+masks staged to smem; plain loop + unroll 8 is the
// form ptxas compiles to 32 regs (occ ~73%) with adequate front-batched MLP.
__global__ void __launch_bounds__(96) emb_kernel(
    const int* __restrict__ sents, const int* __restrict__ seeds,
    const float* __restrict__ mask,
    const float* __restrict__ embT, const float* __restrict__ embS)
{
    __shared__ int   s_tok[L_];
    __shared__ float s_msk[L_];

    const int row = blockIdx.x;
    const int f = threadIdx.x;
    const bool act = (f < 75);
    float4 at = make_float4(0.f, 0.f, 0.f, 0.f);
    float4 as = make_float4(0.f, 0.f, 0.f, 0.f);

    float sc;
    __half* d0;
    __half* d1;

    if (row < B_) {
        if (f < L_) {
            s_tok[f] = sents[row * L_ + f];
            s_msk[f] = mask [row * L_ + f];
        }
        __syncthreads();

        #pragma unroll 8
        for (int l = 0; l < L_; l++) {
            const int tok = s_tok[l];
            const float m = s_msk[l];
            if (act) {
                const float4 vt = *(const float4*)(embT + (size_t)tok * D_ + f * 4);
                const float4 vs = *(const float4*)(embS + (size_t)tok * D_ + f * 4);
                at.x += vt.x * m; at.y += vt.y * m; at.z += vt.z * m; at.w += vt.w * m;
                as.x += vs.x * m; as.y += vs.y * m; as.z += vs.z * m; as.w += vs.w * m;
            }
        }
        float msum = 0.f;
        #pragma unroll
        for (int l = 0; l < L_; l++) msum += s_msk[l];
        sc = 1.f / fmaxf(msum, 1.f);
        d0 = &g_snt[0][row * DP2];
        d1 = &g_snt[1][row * DP2];
    } else {
        const int s = row - B_;
        if (f < LS_) s_tok[f] = seeds[s * LS_ + f];
        __syncthreads();

        #pragma unroll
        for (int l = 0; l < LS_; l++) {
            const int tok = s_tok[l];
            if (act) {
                const float4 vt = *(const float4*)(embT + (size_t)tok * D_ + f * 4);
                const float4 vs = *(const float4*)(embS + (size_t)tok * D_ + f * 4);
                at.x += vt.x; at.y += vt.y; at.z += vt.z; at.w += vt.w;
                as.x += vs.x; as.y += vs.y; as.z += vs.z; as.w += vs.w;
            }
        }
        sc = 1.f / (float)LS_;
        d0 = &g_sd[0][s * DP2];
        d1 = &g_sd[1][s * DP2];
    }

    if (act) {
        ((__half2*)(d0 + f * 4))[0] = __floats2half2_rn(at.x * sc, at.y * sc);
        ((__half2*)(d0 + f * 4))[1] = __floats2half2_rn(at.z * sc, at.w * sc);
        ((__half2*)(d1 + f * 4))[0] = __floats2half2_rn(as.x * sc, as.y * sc);
        ((__half2*)(d1 + f * 4))[1] = __floats2half2_rn(as.z * sc, as.w * sc);
    } else if (f < 80) {
        const __half2 z = __floats2half2_rn(0.f, 0.f);
        ((__half2*)(d0 + f * 4))[0] = z;
        ((__half2*)(d0 + f * 4))[1] = z;
        ((__half2*)(d1 + f * 4))[0] = z;
        ((__half2*)(d1 + f * 4))[1] = z;
    }
}

// ---------------- Stage B: mma.sync fp16 GEMM + per-cluster max ----------------
// Block: 256 threads (8 warps, 2x4), tile 128(m) x 128(n), warp tile 64x32.
// Double-buffered smem stages -> one __syncthreads per K-chunk; STS of chunk
// ch+1 overlaps the MMAs of chunk ch.
__global__ void __launch_bounds__(256, 2) gemm_max_kernel()
{
    extern __shared__ __align__(16) uint4 smem_dyn[];  // [2][2048]: stage s: A@s*2048, B@s*2048+1024

    const int tid = threadIdx.x;
    const int wid = tid >> 5, lane = tid & 31;
    const int warp_m = wid >> 2, warp_n = wid & 3;
    const int z = blockIdx.z, bcol = blockIdx.x, brow = blockIdx.y;

    const __half* Ag = &g_snt[z][(size_t)brow * 128 * DP2];
    const __half* Bg = &g_sd [z][(size_t)bcol * 128 * DP2];

    int srow[4], sidx[4];
    #pragma unroll
    for (int it = 0; it < 4; it++) {
        const int i = it * 256 + tid;
        srow[it] = i >> 3;
        sidx[it] = (i >> 3) * 8 + ((i & 7) ^ ((i >> 3) & 7));
    }

    const uint32_t aBase = smem_u32(smem_dyn);
    const uint32_t bBase = aBase + 16384u;
    uint32_t preA[4]; int a7[4];
    #pragma unroll
    for (int mf = 0; mf < 4; mf++) {
        const int rA = warp_m * 64 + mf * 16 + (lane & 7) + ((lane >> 3) & 1) * 8;
        preA[mf] = aBase + rA * 128;
        a7[mf] = rA & 7;
    }
    const int cA = lane >> 4;
    uint32_t preB[2]; int b7[2];
    #pragma unroll
    for (int g = 0; g < 2; g++) {
        const int rB = warp_n * 32 + g * 16 + (lane & 7) + (lane >> 4) * 8;
        preB[g] = bBase + rB * 128;
        b7[g] = rB & 7;
    }
    const int cB = (lane >> 3) & 1;

    float acc[4][4][4];
    #pragma unroll
    for (int mf = 0; mf < 4; mf++)
        #pragma unroll
        for (int nf = 0; nf < 4; nf++)
            #pragma unroll
            for (int r = 0; r < 4; r++) acc[mf][nf][r] = 0.f;

    // prologue: load + store chunk 0 into stage 0
    uint4 ra[4], rb[4];
    #pragma unroll
    for (int it = 0; it < 4; it++) {
        const int i = it * 256 + tid;
        ra[it] = *(const uint4*)(Ag + (size_t)srow[it] * DP2 + (i & 7) * 8);
        rb[it] = *(const uint4*)(Bg + (size_t)srow[it] * DP2 + (i & 7) * 8);
    }
    #pragma unroll
    for (int it = 0; it < 4; it++) {
        smem_dyn[sidx[it]] = ra[it];
        smem_dyn[1024 + sidx[it]] = rb[it];
    }

    for (int ch = 0; ch < NCHUNK; ch++) {
        if (ch + 1 < NCHUNK) {
            const int kc = (ch + 1) * 64;
            #pragma unroll
            for (int it = 0; it < 4; it++) {
                const int i = it * 256 + tid;
                ra[it] = *(const uint4*)(Ag + (size_t)srow[it] * DP2 + kc + (i & 7) * 8);
                rb[it] = *(const uint4*)(Bg + (size_t)srow[it] * DP2 + kc + (i & 7) * 8);
            }
        }
        __syncthreads();   // stage[ch&1] now visible to all warps

        const uint32_t stOff = (uint32_t)(ch & 1) * 32768u;
        #pragma unroll
        for (int s = 0; s < 4; s++) {
            uint32_t af[4][4];
            #pragma unroll
            for (int mf = 0; mf < 4; mf++) {
                const uint32_t addr = preA[mf] + stOff + ((uint32_t)(((2 * s + cA) ^ a7[mf]) << 4));
                asm volatile("ldmatrix.sync.aligned.m8n8.x4.shared.b16 {%0,%1,%2,%3}, [%4];"
                    : "=r"(af[mf][0]), "=r"(af[mf][1]), "=r"(af[mf][2]), "=r"(af[mf][3])
                    : "r"(addr));
            }
            uint32_t bf[2][4];
            #pragma unroll
            for (int g = 0; g < 2; g++) {
                const uint32_t addr = preB[g] + stOff + ((uint32_t)(((2 * s + cB) ^ b7[g]) << 4));
                asm volatile("ldmatrix.sync.aligned.m8n8.x4.shared.b16 {%0,%1,%2,%3}, [%4];"
                    : "=r"(bf[g][0]), "=r"(bf[g][1]), "=r"(bf[g][2]), "=r"(bf[g][3])
                    : "r"(addr));
            }
            #pragma unroll
            for (int mf = 0; mf < 4; mf++)
                #pragma unroll
                for (int nf = 0; nf < 4; nf++) {
                    const uint32_t b0 = bf[nf >> 1][(nf & 1) * 2 + 0];
                    const uint32_t b1 = bf[nf >> 1][(nf & 1) * 2 + 1];
                    asm volatile(
                        "mma.sync.aligned.m16n8k16.row.col.f32.f16.f16.f32 "
                        "{%0,%1,%2,%3}, {%4,%5,%6,%7}, {%8,%9}, {%0,%1,%2,%3};"
                        : "+f"(acc[mf][nf][0]), "+f"(acc[mf][nf][1]),
                          "+f"(acc[mf][nf][2]), "+f"(acc[mf][nf][3])
                        : "r"(af[mf][0]), "r"(af[mf][1]), "r"(af[mf][2]), "r"(af[mf][3]),
                          "r"(b0), "r"(b1));
                }
        }

        if (ch + 1 < NCHUNK) {
            const uint32_t nx = (uint32_t)((ch + 1) & 1) * 2048u;
            #pragma unroll
            for (int it = 0; it < 4; it++) {
                smem_dyn[nx + sidx[it]] = ra[it];
                smem_dyn[nx + 1024 + sidx[it]] = rb[it];
            }
        }
    }

    const int cluster = bcol * 4 + warp_n;
    #pragma unroll
    for (int mf = 0; mf < 4; mf++) {
        float mlo = -3.402823466e38f, mhi = -3.402823466e38f;
        #pragma unroll
        for (int nf = 0; nf < 4; nf++) {
            mlo = fmaxf(mlo, fmaxf(acc[mf][nf][0], acc[mf][nf][1]));
            mhi = fmaxf(mhi, fmaxf(acc[mf][nf][2], acc[mf][nf][3]));
        }
        mlo = fmaxf(mlo, __shfl_xor_sync(0xffffffffu, mlo, 1));
        mlo = fmaxf(mlo, __shfl_xor_sync(0xffffffffu, mlo, 2));
        mhi = fmaxf(mhi, __shfl_xor_sync(0xffffffffu, mhi, 1));
        mhi = fmaxf(mhi, __shfl_xor_sync(0xffffffffu, mhi, 2));
        if ((lane & 3) == 0) {
            const int grow = brow * 128 + warp_m * 64 + mf * 16 + (lane >> 2);
            g_pmax[z][grow * C_ + cluster] = mlo;
            g_pmax[z][(grow + 8) * C_ + cluster] = mhi;
        }
    }
}

// ---------------- Stage C: warp-per-sentence loss + fused reduction ----------
__global__ void __launch_bounds__(256) loss_kernel(float* __restrict__ out)
{
    const int tid = threadIdx.x;
    const int lane = tid & 31, w = tid >> 5;
    const int b = blockIdx.x * 8 + w;

    const float t0 = g_pmax[0][b * C_ + lane];
    const float t1 = g_pmax[0][b * C_ + 32 + lane];
    const float s0 = g_pmax[1][b * C_ + lane];
    const float s1 = g_pmax[1][b * C_ + 32 + lane];

    float m = fmaxf(t0, t1);
    #pragma unroll
    for (int o = 16; o > 0; o >>= 1)
        m = fmaxf(m, __shfl_xor_sync(0xffffffffu, m, o));

    const float e0 = expf(t0 - m);
    const float e1 = expf(t1 - m);
    float Z = e0 + e1;
    #pragma unroll
    for (int o = 16; o > 0; o >>= 1)
        Z += __shfl_xor_sync(0xffffffffu, Z, o);

    const float inv_Z = 1.f / Z;
    const float reli = inv_Z - (1.f / (float)C_);   // max prob = exp(0)/Z
    const float wgt = 1.f + 0.5f * fabsf(reli);
    const float d0 = e0 * inv_Z - s0;
    const float d1 = e1 * inv_Z - s1;
    float q = d0 * d0 + d1 * d1;
    #pragma unroll
    for (int o = 16; o > 0; o >>= 1)
        q += __shfl_xor_sync(0xffffffffu, q, o);
    if (lane == 0) g_lossb[b] = wgt * q;

    __shared__ int is_last;
    __shared__ float sh[8];
    __threadfence();
    __syncthreads();
    if (tid == 0) {
        const unsigned int o = atomicAdd(&g_cnt, 1u);
        is_last = (o == (unsigned int)(LOSS_BLOCKS - 1));
    }
    __syncthreads();
    if (is_last) {
        __threadfence();
        float sum = 0.f;
        for (int i = tid; i < B_; i += 256) sum += g_lossb[i];
        #pragma unroll
        for (int o = 16; o > 0; o >>= 1)
            sum += __shfl_xor_sync(0xffffffffu, sum, o);
        if (lane == 0) sh[w] = sum;
        __syncthreads();
        if (tid == 0) {
            float tot = 0.f;
            #pragma unroll
            for (int i = 0; i < 8; i++) tot += sh[i];
            out[0] = tot * (1.f / (float)B_);
            g_cnt = 0;   // reset for next graph replay
        }
    }
}

extern "C" void kernel_launch(void* const* d_in, const int* in_sizes, int n_in,
                              void* d_out, int out_size)
{
    const int* sents = nullptr;
    const int* seeds = nullptr;
    const float* mask = nullptr;
    const float* embT = nullptr;
    const float* embS = nullptr;
    int c131 = 0, c15m = 0;
    for (int i = 0; i < n_in; i++) {
        const int sz = in_sizes[i];
        if (sz == B_ * L_) {
            if (c131 == 0) sents = (const int*)d_in[i];
            else           mask  = (const float*)d_in[i];
            c131++;
        } else if (sz == S_ * LS_) {
            seeds = (const int*)d_in[i];
        } else if (sz == 50000 * D_) {
            if (c15m == 0) embT = (const float*)d_in[i];
            else           embS = (const float*)d_in[i];
            c15m++;
        }
    }

    cudaFuncSetAttribute(gemm_max_kernel,
                         cudaFuncAttributeMaxDynamicSharedMemorySize, GEMM_SMEM);

    emb_kernel<<<B_ + S_, 96>>>(sents, seeds, mask, embT, embS);
    gemm_max_kernel<<<dim3(16, 16, 2), 256, GEMM_SMEM>>>();
    loss_kernel<<<LOSS_BLOCKS, 256>>>((float*)d_out);
}